// round 6
// baseline (speedup 1.0000x reference)
#include <cuda_runtime.h>
#include <math.h>
#include <stdint.h>

#define BATCH 8192
#define NN 4096
#define LDB 68           // padded stride (floats), float4-aligned
#define EPSF 1e-8f

#define K0_BLOCKS 256
#define K0_NB 32
#define K2_BLOCKS 2048
#define K2_NB 4
#define SWEEPS_BATCH 7
#define SWEEPS_SMALL 8
#define SWEEPS_TS 8

// ---------------- device scratch ----------------
__device__ __align__(256) float g_partial_mean[(size_t)K0_BLOCKS * NN];
__device__ __align__(256) float g_mean[NN];
__device__ __align__(256) float g_s[NN];
__device__ __align__(256) float g_si[NN];
__device__ __align__(256) float g_gsqrt[NN];
__device__ __align__(256) float g_W[NN];
__device__ __align__(256) float g_WT[NN];
__device__ __align__(256) float g_partial_t[(size_t)K2_BLOCKS * NN];
__device__ __align__(256) float g_tmean[NN];

// ---------------- packed f32x2 helpers ----------------
typedef unsigned long long u64;
__device__ __forceinline__ u64 pk2(float x, float y) {
    u64 r; asm("mov.b64 %0,{%1,%2};" : "=l"(r) : "f"(x), "f"(y)); return r;
}
__device__ __forceinline__ void up2(u64 v, float& x, float& y) {
    asm("mov.b64 {%0,%1},%2;" : "=f"(x), "=f"(y) : "l"(v));
}
__device__ __forceinline__ u64 fma2(u64 a, u64 b, u64 c) {
    u64 d; asm("fma.rn.f32x2 %0,%1,%2,%3;" : "=l"(d) : "l"(a), "l"(b), "l"(c)); return d;
}
__device__ __forceinline__ u64 mul2(u64 a, u64 b) {
    u64 d; asm("mul.rn.f32x2 %0,%1,%2;" : "=l"(d) : "l"(a), "l"(b)); return d;
}

// ================= 256-thread helpers (side kernels) =================

__device__ __forceinline__ void load_tile(const float* __restrict__ g, float* __restrict__ s) {
    for (int i = threadIdx.x; i < 1024; i += 256) {
        int r = i >> 4, c4 = (i & 15) << 2;
        *(float4*)&s[r * LDB + c4] = *(const float4*)&g[(r << 6) + c4];
    }
}
__device__ __forceinline__ void store_tile(const float* __restrict__ s, float* __restrict__ g) {
    for (int i = threadIdx.x; i < 1024; i += 256) {
        int r = i >> 4, c4 = (i & 15) << 2;
        *(float4*)&g[(r << 6) + c4] = *(const float4*)&s[r * LDB + c4];
    }
}

__device__ __forceinline__ void mm64f4(const float* __restrict__ A, const float* __restrict__ B,
                                       float* __restrict__ C, int cstride) {
    const int r = threadIdx.x >> 2;
    const int c0 = (threadIdx.x & 3) << 4;
    u64 acc[8];
#pragma unroll
    for (int i = 0; i < 8; ++i) acc[i] = 0ull;
#pragma unroll 4
    for (int k = 0; k < 64; ++k) {
        float a = A[r * LDB + k];
        u64 a2 = pk2(a, a);
        const ulonglong2* br = (const ulonglong2*)(B + k * LDB + c0);
        ulonglong2 b0 = br[0], b1 = br[1], b2 = br[2], b3 = br[3];
        acc[0] = fma2(a2, b0.x, acc[0]); acc[1] = fma2(a2, b0.y, acc[1]);
        acc[2] = fma2(a2, b1.x, acc[2]); acc[3] = fma2(a2, b1.y, acc[3]);
        acc[4] = fma2(a2, b2.x, acc[4]); acc[5] = fma2(a2, b2.y, acc[5]);
        acc[6] = fma2(a2, b3.x, acc[6]); acc[7] = fma2(a2, b3.y, acc[7]);
    }
    ulonglong2* cp = (ulonglong2*)(C + r * cstride + c0);
    cp[0] = make_ulonglong2(acc[0], acc[1]); cp[1] = make_ulonglong2(acc[2], acc[3]);
    cp[2] = make_ulonglong2(acc[4], acc[5]); cp[3] = make_ulonglong2(acc[6], acc[7]);
}

__device__ __forceinline__ void gram_scaled(const float* __restrict__ Bs, const float* __restrict__ B,
                                            float* __restrict__ out, int ostride) {
    const int r = threadIdx.x >> 2;
    const int c0 = (threadIdx.x & 3) << 4;
    u64 acc[8];
#pragma unroll
    for (int i = 0; i < 8; ++i) acc[i] = 0ull;
#pragma unroll 4
    for (int j = 0; j < 64; ++j) {
        float u = Bs[j * LDB + r];
        u64 u2 = pk2(u, u);
        const ulonglong2* br = (const ulonglong2*)(B + j * LDB + c0);
        ulonglong2 b0 = br[0], b1 = br[1], b2 = br[2], b3 = br[3];
        acc[0] = fma2(u2, b0.x, acc[0]); acc[1] = fma2(u2, b0.y, acc[1]);
        acc[2] = fma2(u2, b1.x, acc[2]); acc[3] = fma2(u2, b1.y, acc[3]);
        acc[4] = fma2(u2, b2.x, acc[4]); acc[5] = fma2(u2, b2.y, acc[5]);
        acc[6] = fma2(u2, b3.x, acc[6]); acc[7] = fma2(u2, b3.y, acc[7]);
    }
    ulonglong2* op = (ulonglong2*)(out + r * ostride + c0);
    op[0] = make_ulonglong2(acc[0], acc[1]); op[1] = make_ulonglong2(acc[2], acc[3]);
    op[2] = make_ulonglong2(acc[4], acc[5]); op[3] = make_ulonglong2(acc[6], acc[7]);
}

__device__ __forceinline__ float colnrm2(const float* __restrict__ B, int j, int seg, float4 v[4]) {
    const float4* c = (const float4*)(B + j * LDB + (seg << 4));
    v[0] = c[0]; v[1] = c[1]; v[2] = c[2]; v[3] = c[3];
    float n = v[0].x * v[0].x;
    n = fmaf(v[0].y, v[0].y, n); n = fmaf(v[0].z, v[0].z, n); n = fmaf(v[0].w, v[0].w, n);
    n = fmaf(v[1].x, v[1].x, n); n = fmaf(v[1].y, v[1].y, n); n = fmaf(v[1].z, v[1].z, n); n = fmaf(v[1].w, v[1].w, n);
    n = fmaf(v[2].x, v[2].x, n); n = fmaf(v[2].y, v[2].y, n); n = fmaf(v[2].z, v[2].z, n); n = fmaf(v[2].w, v[2].w, n);
    n = fmaf(v[3].x, v[3].x, n); n = fmaf(v[3].y, v[3].y, n); n = fmaf(v[3].z, v[3].z, n); n = fmaf(v[3].w, v[3].w, n);
    n += __shfl_xor_sync(0xffffffffu, n, 1);
    n += __shfl_xor_sync(0xffffffffu, n, 2);
    return n;
}

__device__ __forceinline__ void scale_store(float* __restrict__ D, int j, int seg,
                                            const float4 v[4], float f) {
    float4* d = (float4*)(D + j * LDB + (seg << 4));
    d[0] = make_float4(f * v[0].x, f * v[0].y, f * v[0].z, f * v[0].w);
    d[1] = make_float4(f * v[1].x, f * v[1].y, f * v[1].z, f * v[1].w);
    d[2] = make_float4(f * v[2].x, f * v[2].y, f * v[2].z, f * v[2].w);
    d[3] = make_float4(f * v[3].x, f * v[3].y, f * v[3].z, f * v[3].w);
}

// 256-thread one-sided Jacobi with tracked norms (1 pair per octet)
__device__ void jacobi_onesided(float* __restrict__ B, float* __restrict__ nbuf, int sweeps) {
    const int tid = threadIdx.x;
    const int k = tid >> 3;
    const int o0 = (tid & 7) << 2;
    const int o1 = 32 + o0;
    const int jn = tid >> 2, segn = tid & 3;
    for (int sw = 0; sw < sweeps; ++sw) {
        {
            float4 v[4];
            float n = colnrm2(B, jn, segn, v);
            if (segn == 0) nbuf[jn] = n;
        }
        __syncthreads();
        int p = (k == 0) ? 0 : k;
        int q = 63 - k;
        for (int rr = 0; rr < 63; ++rr) {
            float* bp = B + p * LDB;
            float* bq = B + q * LDB;
            ulonglong2 P0 = *(ulonglong2*)(bp + o0), P1 = *(ulonglong2*)(bp + o1);
            ulonglong2 Q0 = *(ulonglong2*)(bq + o0), Q1 = *(ulonglong2*)(bq + o1);
            u64 spq = mul2(P0.x, Q0.x);
            spq = fma2(P0.y, Q0.y, spq); spq = fma2(P1.x, Q1.x, spq); spq = fma2(P1.y, Q1.y, spq);
            float a0, a1;
            up2(spq, a0, a1);
            float apq = a0 + a1;
            apq += __shfl_xor_sync(0xffffffffu, apq, 1);
            apq += __shfl_xor_sync(0xffffffffu, apq, 2);
            apq += __shfl_xor_sync(0xffffffffu, apq, 4);
            float app = nbuf[p], aqq = nbuf[q];
            float c, s, t;
            if (fabsf(apq) > 1e-30f) {
                float zeta = (aqq - app) / (2.0f * apq);
                t = copysignf(1.0f, zeta) / (fabsf(zeta) + sqrtf(fmaf(zeta, zeta, 1.0f)));
                c = rsqrtf(fmaf(t, t, 1.0f));
                s = t * c;
            } else { c = 1.0f; s = 0.0f; t = 0.0f; }
            u64 c2 = pk2(c, c), s2 = pk2(s, s), ns2 = pk2(-s, -s);
            ulonglong2 NP0, NP1, NQ0, NQ1;
            NP0.x = fma2(c2, P0.x, mul2(ns2, Q0.x));
            NP0.y = fma2(c2, P0.y, mul2(ns2, Q0.y));
            NP1.x = fma2(c2, P1.x, mul2(ns2, Q1.x));
            NP1.y = fma2(c2, P1.y, mul2(ns2, Q1.y));
            NQ0.x = fma2(s2, P0.x, mul2(c2, Q0.x));
            NQ0.y = fma2(s2, P0.y, mul2(c2, Q0.y));
            NQ1.x = fma2(s2, P1.x, mul2(c2, Q1.x));
            NQ1.y = fma2(s2, P1.y, mul2(c2, Q1.y));
            *(ulonglong2*)(bp + o0) = NP0; *(ulonglong2*)(bp + o1) = NP1;
            *(ulonglong2*)(bq + o0) = NQ0; *(ulonglong2*)(bq + o1) = NQ1;
            if ((tid & 7) == 0) {
                float d = t * apq;
                nbuf[p] = app - d;
                nbuf[q] = aqq + d;
            }
            if (k) p = (p == 63) ? 1 : p + 1;
            q = (q == 63) ? 1 : q + 1;
            __syncthreads();
        }
    }
}

// two-sided Jacobi (only for indefinite tmean)
__device__ void jacobi_twosided(float* __restrict__ A, float* __restrict__ VT,
                                float* cbuf, float* sbuf, int sweeps) {
    const int tid = threadIdx.x;
    for (int idx = tid; idx < NN; idx += 256) {
        int r = idx >> 6, c = idx & 63;
        VT[r * LDB + c] = (r == c) ? 1.f : 0.f;
    }
    __syncthreads();
    for (int sw = 0; sw < sweeps; ++sw) {
        for (int rr = 0; rr < 63; ++rr) {
            if (tid < 32) {
                int p = (tid == 0) ? 0 : 1 + (tid - 1 + rr) % 63;
                int q = 1 + (62 - tid + rr) % 63;
                float app = A[p * LDB + p], aqq = A[q * LDB + q], apq = A[p * LDB + q];
                float c, s;
                if (fabsf(apq) > 1e-30f) {
                    float th = 0.5f * (aqq - app) / apq;
                    float t = copysignf(1.f, th) / (fabsf(th) + sqrtf(fmaf(th, th, 1.f)));
                    c = rsqrtf(fmaf(t, t, 1.f)); s = t * c;
                } else { c = 1.f; s = 0.f; }
                cbuf[tid] = c; sbuf[tid] = s;
            }
            __syncthreads();
            for (int u = tid; u < 1536; u += 256) {
                if (u < 1024) {
                    int ki = u & 31, kj = u >> 5;
                    int pi = (ki == 0) ? 0 : 1 + (ki - 1 + rr) % 63, qi = 1 + (62 - ki + rr) % 63;
                    int pj = (kj == 0) ? 0 : 1 + (kj - 1 + rr) % 63, qj = 1 + (62 - kj + rr) % 63;
                    float ci = cbuf[ki], si = sbuf[ki], cj = cbuf[kj], sj = sbuf[kj];
                    float a00 = A[pi * LDB + pj], a01 = A[pi * LDB + qj];
                    float a10 = A[qi * LDB + pj], a11 = A[qi * LDB + qj];
                    float b00 = ci * a00 - si * a10, b01 = ci * a01 - si * a11;
                    float b10 = si * a00 + ci * a10, b11 = si * a01 + ci * a11;
                    A[pi * LDB + pj] = cj * b00 - sj * b01;
                    A[pi * LDB + qj] = sj * b00 + cj * b01;
                    A[qi * LDB + pj] = cj * b10 - sj * b11;
                    A[qi * LDB + qj] = sj * b10 + cj * b11;
                } else {
                    int w = u - 1024;
                    int kk = w >> 4, c4 = (w & 15) << 2;
                    int p = (kk == 0) ? 0 : 1 + (kk - 1 + rr) % 63, q = 1 + (62 - kk + rr) % 63;
                    float c = cbuf[kk], s = sbuf[kk];
                    float4 vp = *(float4*)&VT[p * LDB + c4];
                    float4 vq = *(float4*)&VT[q * LDB + c4];
                    float4 np, nq;
                    np.x = c*vp.x - s*vq.x; np.y = c*vp.y - s*vq.y; np.z = c*vp.z - s*vq.z; np.w = c*vp.w - s*vq.w;
                    nq.x = s*vp.x + c*vq.x; nq.y = s*vp.y + c*vq.y; nq.z = s*vp.z + c*vq.z; nq.w = s*vp.w + c*vq.w;
                    *(float4*)&VT[p * LDB + c4] = np;
                    *(float4*)&VT[q * LDB + c4] = nq;
                }
            }
            __syncthreads();
        }
    }
}

// ================= 128-thread helpers (batch kernel) =================

// C = A @ B for 128 threads: thread -> row r = tid>>1, 32 cols at c0 = (tid&1)*32
__device__ __forceinline__ void mm64_128(const float* __restrict__ A, const float* __restrict__ B,
                                         float* __restrict__ C) {
    const int r = threadIdx.x >> 1;
    const int c0 = (threadIdx.x & 1) << 5;
    u64 acc[16];
#pragma unroll
    for (int i = 0; i < 16; ++i) acc[i] = 0ull;
#pragma unroll 2
    for (int k = 0; k < 64; ++k) {
        float a = A[r * LDB + k];
        u64 a2 = pk2(a, a);
        const ulonglong2* br = (const ulonglong2*)(B + k * LDB + c0);
#pragma unroll
        for (int i = 0; i < 8; ++i) {
            ulonglong2 b = br[i];
            acc[2 * i]     = fma2(a2, b.x, acc[2 * i]);
            acc[2 * i + 1] = fma2(a2, b.y, acc[2 * i + 1]);
        }
    }
    ulonglong2* cp = (ulonglong2*)(C + r * LDB + c0);
#pragma unroll
    for (int i = 0; i < 8; ++i) cp[i] = make_ulonglong2(acc[2 * i], acc[2 * i + 1]);
}

// 128-thread one-sided Jacobi: octet (tid>>3, 16 octets) owns pairs k and k+16.
// Lane sub=tid&7 handles rows [4s,4s+4) and [32+4s,32+4s+4) (conflict-free).
__device__ void jacobi128(float* __restrict__ B, float* __restrict__ nbuf, int sweeps) {
    const int tid = threadIdx.x;
    const int k1 = tid >> 3;          // 0..15
    const int k2 = k1 + 16;           // 16..31
    const int o0 = (tid & 7) << 2;
    const int o1 = 32 + o0;
    const unsigned rmask = 0xFFu << ((tid & 31) & ~7);
    const int jn = tid >> 1;
    const int hn = (tid & 1) << 5;
    for (int sw = 0; sw < sweeps; ++sw) {
        // refresh norms: thread-pair per column, 32 rows each
        {
            const float4* cc = (const float4*)(B + jn * LDB + hn);
            float n = 0.f;
#pragma unroll
            for (int i = 0; i < 8; ++i) {
                float4 v = cc[i];
                n = fmaf(v.x, v.x, n); n = fmaf(v.y, v.y, n);
                n = fmaf(v.z, v.z, n); n = fmaf(v.w, v.w, n);
            }
            n += __shfl_xor_sync(0xffffffffu, n, 1);
            if ((tid & 1) == 0) nbuf[jn] = n;
        }
        __syncthreads();
        int p1 = (k1 == 0) ? 0 : k1, q1 = 63 - k1;
        int p2 = k2, q2 = 63 - k2;
        for (int rr = 0; rr < 63; ++rr) {
            float* bp1 = B + p1 * LDB; float* bq1 = B + q1 * LDB;
            float* bp2 = B + p2 * LDB; float* bq2 = B + q2 * LDB;
            ulonglong2 P10 = *(ulonglong2*)(bp1 + o0), P11 = *(ulonglong2*)(bp1 + o1);
            ulonglong2 Q10 = *(ulonglong2*)(bq1 + o0), Q11 = *(ulonglong2*)(bq1 + o1);
            ulonglong2 P20 = *(ulonglong2*)(bp2 + o0), P21 = *(ulonglong2*)(bp2 + o1);
            ulonglong2 Q20 = *(ulonglong2*)(bq2 + o0), Q21 = *(ulonglong2*)(bq2 + o1);
            u64 d1 = mul2(P10.x, Q10.x);
            d1 = fma2(P10.y, Q10.y, d1); d1 = fma2(P11.x, Q11.x, d1); d1 = fma2(P11.y, Q11.y, d1);
            u64 d2 = mul2(P20.x, Q20.x);
            d2 = fma2(P20.y, Q20.y, d2); d2 = fma2(P21.x, Q21.x, d2); d2 = fma2(P21.y, Q21.y, d2);
            float a0, a1;
            up2(d1, a0, a1); float apq1 = a0 + a1;
            up2(d2, a0, a1); float apq2 = a0 + a1;
            apq1 += __shfl_xor_sync(0xffffffffu, apq1, 1);
            apq2 += __shfl_xor_sync(0xffffffffu, apq2, 1);
            apq1 += __shfl_xor_sync(0xffffffffu, apq1, 2);
            apq2 += __shfl_xor_sync(0xffffffffu, apq2, 2);
            apq1 += __shfl_xor_sync(0xffffffffu, apq1, 4);
            apq2 += __shfl_xor_sync(0xffffffffu, apq2, 4);
            float app1 = nbuf[p1], aqq1 = nbuf[q1];
            float app2 = nbuf[p2], aqq2 = nbuf[q2];
            float c1, s1, t1;
            if (fabsf(apq1) > 1e-30f) {
                float z = (aqq1 - app1) / (2.0f * apq1);
                t1 = copysignf(1.0f, z) / (fabsf(z) + sqrtf(fmaf(z, z, 1.0f)));
                c1 = rsqrtf(fmaf(t1, t1, 1.0f)); s1 = t1 * c1;
            } else { c1 = 1.0f; s1 = 0.0f; t1 = 0.0f; }
            float c2f, s2f, t2;
            if (fabsf(apq2) > 1e-30f) {
                float z = (aqq2 - app2) / (2.0f * apq2);
                t2 = copysignf(1.0f, z) / (fabsf(z) + sqrtf(fmaf(z, z, 1.0f)));
                c2f = rsqrtf(fmaf(t2, t2, 1.0f)); s2f = t2 * c2f;
            } else { c2f = 1.0f; s2f = 0.0f; t2 = 0.0f; }
            {
                u64 cc = pk2(c1, c1), ss = pk2(s1, s1), ns = pk2(-s1, -s1);
                ulonglong2 NP0, NP1, NQ0, NQ1;
                NP0.x = fma2(cc, P10.x, mul2(ns, Q10.x));
                NP0.y = fma2(cc, P10.y, mul2(ns, Q10.y));
                NP1.x = fma2(cc, P11.x, mul2(ns, Q11.x));
                NP1.y = fma2(cc, P11.y, mul2(ns, Q11.y));
                NQ0.x = fma2(ss, P10.x, mul2(cc, Q10.x));
                NQ0.y = fma2(ss, P10.y, mul2(cc, Q10.y));
                NQ1.x = fma2(ss, P11.x, mul2(cc, Q11.x));
                NQ1.y = fma2(ss, P11.y, mul2(cc, Q11.y));
                *(ulonglong2*)(bp1 + o0) = NP0; *(ulonglong2*)(bp1 + o1) = NP1;
                *(ulonglong2*)(bq1 + o0) = NQ0; *(ulonglong2*)(bq1 + o1) = NQ1;
            }
            {
                u64 cc = pk2(c2f, c2f), ss = pk2(s2f, s2f), ns = pk2(-s2f, -s2f);
                ulonglong2 NP0, NP1, NQ0, NQ1;
                NP0.x = fma2(cc, P20.x, mul2(ns, Q20.x));
                NP0.y = fma2(cc, P20.y, mul2(ns, Q20.y));
                NP1.x = fma2(cc, P21.x, mul2(ns, Q21.x));
                NP1.y = fma2(cc, P21.y, mul2(ns, Q21.y));
                NQ0.x = fma2(ss, P20.x, mul2(cc, Q20.x));
                NQ0.y = fma2(ss, P20.y, mul2(cc, Q20.y));
                NQ1.x = fma2(ss, P21.x, mul2(cc, Q21.x));
                NQ1.y = fma2(ss, P21.y, mul2(cc, Q21.y));
                *(ulonglong2*)(bp2 + o0) = NP0; *(ulonglong2*)(bp2 + o1) = NP1;
                *(ulonglong2*)(bq2 + o0) = NQ0; *(ulonglong2*)(bq2 + o1) = NQ1;
            }
            if ((tid & 7) == 0) {
                float e1 = t1 * apq1, e2 = t2 * apq2;
                nbuf[p1] = app1 - e1; nbuf[q1] = aqq1 + e1;
                nbuf[p2] = app2 - e2; nbuf[q2] = aqq2 + e2;
            }
            if (k1) p1 = (p1 == 63) ? 1 : p1 + 1;
            q1 = (q1 == 63) ? 1 : q1 + 1;
            p2 = (p2 == 63) ? 1 : p2 + 1;
            q2 = (q2 == 63) ? 1 : q2 + 1;
            __syncthreads();
        }
    }
}

// ---------------- kernel 0: arithmetic mean ----------------
__global__ __launch_bounds__(256) void mean_partial_kernel(const float* __restrict__ x) {
    const int g = blockIdx.x, tid = threadIdx.x;
    float4 acc[4] = {{0,0,0,0},{0,0,0,0},{0,0,0,0},{0,0,0,0}};
    const float4* xb = (const float4*)(x + (size_t)g * K0_NB * NN);
    for (int b = 0; b < K0_NB; ++b) {
#pragma unroll
        for (int i = 0; i < 4; ++i) {
            float4 v = xb[(size_t)b * 1024 + tid + (i << 8)];
            acc[i].x += v.x; acc[i].y += v.y; acc[i].z += v.z; acc[i].w += v.w;
        }
    }
    float4* pm = (float4*)(g_partial_mean + (size_t)g * NN);
#pragma unroll
    for (int i = 0; i < 4; ++i) pm[tid + (i << 8)] = acc[i];
}

__global__ void reduce_mean_kernel() {
    int j = blockIdx.x * 128 + threadIdx.x;
    float acc = 0.f;
    for (int g = 0; g < K0_BLOCKS; ++g) acc += g_partial_mean[(size_t)g * NN + j];
    g_mean[j] = acc * (1.0f / BATCH);
}

// ---------------- kernel 1: eigh(mean)->s,si ; eigh(G)->gsqrt ----------------
__global__ __launch_bounds__(256) void prep_kernel(const float* __restrict__ G) {
    extern __shared__ float sm[];
    float* A    = sm;
    float* Bsc  = A + 4352;
    float* nbuf = Bsc + 4352;
    const int tid = threadIdx.x;
    load_tile(blockIdx.x == 0 ? g_mean : G, A);
    __syncthreads();
    jacobi_onesided(A, nbuf, SWEEPS_SMALL);
    const int j = tid >> 2, seg = tid & 3;
    float4 v[4];
    float n = colnrm2(A, j, seg, v);
    float lam = fmaxf(sqrtf(n), EPSF);
    float inv_n = 1.0f / n;
    scale_store(Bsc, j, seg, v, sqrtf(lam) * inv_n);
    __syncthreads();
    gram_scaled(Bsc, A, blockIdx.x == 0 ? g_s : g_gsqrt, 64);
    if (blockIdx.x == 0) {
        __syncthreads();
        scale_store(Bsc, j, seg, v, rsqrtf(lam) * inv_n);
        __syncthreads();
        gram_scaled(Bsc, A, g_si, 64);
    }
}

// ---------------- kernel 2: per-batch logm(si x si), partial sums (128 thr) ----------------
__global__ __launch_bounds__(128, 4) void batch_log_kernel(const float* __restrict__ x) {
    extern __shared__ float sm[];
    float* sis  = sm;            // 4352
    float* b1   = sis + 4352;    // 4352
    float* b2   = b1 + 4352;     // 4352
    float* fbuf = b2 + 4352;     // 64
    float* nbuf = fbuf + 64;     // 64
    const int tid = threadIdx.x;
    for (int i = tid; i < 1024; i += 128) {
        int rr = i >> 4, c4 = (i & 15) << 2;
        *(float4*)&sis[rr * LDB + c4] = *(const float4*)&g_si[(rr << 6) + c4];
    }
    __syncthreads();
    const int r = tid >> 1;
    const int c0 = (tid & 1) << 5;
    u64 tacc[16];
#pragma unroll
    for (int i = 0; i < 16; ++i) tacc[i] = 0ull;

    for (int m = 0; m < K2_NB; ++m) {
        const float* xb = x + ((size_t)blockIdx.x * K2_NB + m) * NN;
        for (int i = tid; i < 1024; i += 128) {
            int rr = i >> 4, c4 = (i & 15) << 2;
            *(float4*)&b1[rr * LDB + c4] = *(const float4*)&xb[(rr << 6) + c4];
        }
        __syncthreads();
        mm64_128(sis, b1, b2);  __syncthreads();   // P = si @ x
        mm64_128(b2, sis, b1);  __syncthreads();   // A = P @ si (symmetric)
        jacobi128(b1, nbuf, SWEEPS_BATCH);         // cols b_j = lam_j u_j
        {
            const float4* cc = (const float4*)(b1 + r * LDB + c0);
            float n = 0.f;
#pragma unroll
            for (int i = 0; i < 8; ++i) {
                float4 v = cc[i];
                n = fmaf(v.x, v.x, n); n = fmaf(v.y, v.y, n);
                n = fmaf(v.z, v.z, n); n = fmaf(v.w, v.w, n);
            }
            n += __shfl_xor_sync(0xffffffffu, n, 1);
            if ((tid & 1) == 0) {
                float lam = sqrtf(n);
                fbuf[r] = logf(fmaxf(lam, EPSF)) / n;   // log(lam)/lam^2
            }
        }
        __syncthreads();
        {   // tacc += sum_j f_j * b_j b_j^T  (row r, cols c0..c0+31)
#pragma unroll 2
            for (int jj = 0; jj < 64; ++jj) {
                float u = fbuf[jj] * b1[jj * LDB + r];
                u64 u2 = pk2(u, u);
                const ulonglong2* br = (const ulonglong2*)(b1 + jj * LDB + c0);
#pragma unroll
                for (int i = 0; i < 8; ++i) {
                    ulonglong2 b = br[i];
                    tacc[2 * i]     = fma2(u2, b.x, tacc[2 * i]);
                    tacc[2 * i + 1] = fma2(u2, b.y, tacc[2 * i + 1]);
                }
            }
        }
        __syncthreads();
    }
    ulonglong2* pt = (ulonglong2*)(g_partial_t + (size_t)blockIdx.x * NN + (r << 6) + c0);
#pragma unroll
    for (int i = 0; i < 8; ++i) pt[i] = make_ulonglong2(tacc[2 * i], tacc[2 * i + 1]);
}

__global__ void reduce_t_kernel() {
    int j = blockIdx.x * 128 + threadIdx.x;
    float acc = 0.f;
    for (int g = 0; g < K2_BLOCKS; ++g) acc += g_partial_t[(size_t)g * NN + j];
    g_tmean[j] = acc * (1.0f / BATCH);
}

// ---------------- kernel 3: expm(tmean), center, csi, W, WT ----------------
__global__ __launch_bounds__(256) void center_kernel() {
    extern __shared__ float sm[];
    float* A  = sm;
    float* VT = A + 4352;
    float* T1 = VT + 4352;
    float* T2 = T1 + 4352;
    float* fw = T2 + 4352;
    float* cb = fw + 64;
    float* sb = cb + 32;
    float* nbuf = sb + 32;
    const int tid = threadIdx.x;

    load_tile(g_tmean, A);
    __syncthreads();
    jacobi_twosided(A, VT, cb, sb, SWEEPS_TS);
    if (tid < 64) fw[tid] = expf(A[tid * LDB + tid]);
    __syncthreads();
    for (int idx = tid; idx < NN; idx += 256) {
        int k2 = idx >> 6, i = idx & 63;
        T1[k2 * LDB + i] = fw[k2] * VT[k2 * LDB + i];
    }
    __syncthreads();
    gram_scaled(T1, VT, T2, LDB);       // T2 = expm(tmean)
    __syncthreads();
    load_tile(g_s, A);
    __syncthreads();
    mm64f4(A, T2, T1, LDB);  __syncthreads();  // T1 = s E
    mm64f4(T1, A, T2, LDB);  __syncthreads();  // T2 = center (SPD)
    jacobi_onesided(T2, nbuf, SWEEPS_SMALL);
    {
        const int j = tid >> 2, seg = tid & 3;
        float4 v[4];
        float n = colnrm2(T2, j, seg, v);
        float lam = fmaxf(sqrtf(n), EPSF);
        float f = rsqrtf(lam) / n;
        scale_store(T1, j, seg, v, f);
    }
    __syncthreads();
    gram_scaled(T1, T2, A, LDB);        // A = csi
    __syncthreads();
    load_tile(g_gsqrt, VT);
    __syncthreads();
    mm64f4(VT, A, T1, LDB);             // T1 = g_sqrt @ csi = W
    __syncthreads();
    store_tile(T1, g_W);
    for (int idx = tid; idx < NN; idx += 256) {
        int rr = idx >> 6, cc = idx & 63;
        g_WT[(cc << 6) + rr] = T1[rr * LDB + cc];
    }
}

// ---------------- kernel 4: out_b = W x_b W^T ----------------
__global__ __launch_bounds__(256) void output_kernel(const float* __restrict__ x,
                                                     float* __restrict__ out) {
    extern __shared__ float sm[];
    float* Ws = sm;
    float* WT = Ws + 4352;
    float* xs = WT + 4352;
    float* P  = xs + 4352;
    load_tile(g_W, Ws);
    load_tile(g_WT, WT);
    load_tile(x + (size_t)blockIdx.x * NN, xs);
    __syncthreads();
    mm64f4(Ws, xs, P, LDB);             // P = W @ x
    __syncthreads();
    mm64f4(P, WT, out + (size_t)blockIdx.x * NN, 64);   // out = P @ W^T
}

// ---------------- launcher ----------------
extern "C" void kernel_launch(void* const* d_in, const int* in_sizes, int n_in,
                              void* d_out, int out_size) {
    const float* x;
    const float* G;
    if (in_sizes[0] == NN) { G = (const float*)d_in[0]; x = (const float*)d_in[1]; }
    else                   { x = (const float*)d_in[0]; G = (const float*)d_in[1]; }
    float* out = (float*)d_out;

    constexpr size_t SM_PREP   = (size_t)(2 * 4352 + 64) * 4;
    constexpr size_t SM_BATCH  = (size_t)(3 * 4352 + 64 + 64) * 4;
    constexpr size_t SM_CENTER = (size_t)(4 * 4352 + 64 + 32 + 32 + 64) * 4;
    constexpr size_t SM_OUT    = (size_t)(4 * 4352) * 4;

    cudaFuncSetAttribute(batch_log_kernel, cudaFuncAttributeMaxDynamicSharedMemorySize, (int)SM_BATCH);
    cudaFuncSetAttribute(center_kernel,    cudaFuncAttributeMaxDynamicSharedMemorySize, (int)SM_CENTER);
    cudaFuncSetAttribute(output_kernel,    cudaFuncAttributeMaxDynamicSharedMemorySize, (int)SM_OUT);

    mean_partial_kernel<<<K0_BLOCKS, 256>>>(x);
    reduce_mean_kernel<<<32, 128>>>();
    prep_kernel<<<2, 256, SM_PREP>>>(G);
    batch_log_kernel<<<K2_BLOCKS, 128, SM_BATCH>>>(x);
    reduce_t_kernel<<<32, 128>>>();
    center_kernel<<<1, 256, SM_CENTER>>>();
    output_kernel<<<BATCH, 256, SM_OUT>>>(x, out);
}

// round 7
// speedup vs baseline: 1.7674x; 1.7674x over previous
#include <cuda_runtime.h>
#include <math.h>
#include <stdint.h>

#define BATCH 8192
#define NN 4096
#define LDB 68           // padded stride (floats), float4-aligned
#define EPSF 1e-8f
#define SKIP_TAU 1e-6f

#define K0_BLOCKS 256
#define K0_NB 32
#define K2_BLOCKS 2048
#define K2_NB 4
#define SWEEPS_BATCH 7
#define SWEEPS_SMALL 8
#define SWEEPS_TS 8

// ---------------- device scratch ----------------
__device__ __align__(256) float g_partial_mean[(size_t)K0_BLOCKS * NN];
__device__ __align__(256) float g_mean[NN];
__device__ __align__(256) float g_s[NN];
__device__ __align__(256) float g_si[NN];
__device__ __align__(256) float g_gsqrt[NN];
__device__ __align__(256) float g_W[NN];
__device__ __align__(256) float g_WT[NN];
__device__ __align__(256) float g_partial_t[(size_t)K2_BLOCKS * NN];
__device__ __align__(256) float g_tmean[NN];

// ---------------- packed f32x2 helpers ----------------
typedef unsigned long long u64;
__device__ __forceinline__ u64 pk2(float x, float y) {
    u64 r; asm("mov.b64 %0,{%1,%2};" : "=l"(r) : "f"(x), "f"(y)); return r;
}
__device__ __forceinline__ void up2(u64 v, float& x, float& y) {
    asm("mov.b64 {%0,%1},%2;" : "=f"(x), "=f"(y) : "l"(v));
}
__device__ __forceinline__ u64 fma2(u64 a, u64 b, u64 c) {
    u64 d; asm("fma.rn.f32x2 %0,%1,%2,%3;" : "=l"(d) : "l"(a), "l"(b), "l"(c)); return d;
}
__device__ __forceinline__ u64 mul2(u64 a, u64 b) {
    u64 d; asm("mul.rn.f32x2 %0,%1,%2;" : "=l"(d) : "l"(a), "l"(b)); return d;
}

// ---------------- tile movement (256 threads) ----------------
__device__ __forceinline__ void load_tile(const float* __restrict__ g, float* __restrict__ s) {
    for (int i = threadIdx.x; i < 1024; i += 256) {
        int r = i >> 4, c4 = (i & 15) << 2;
        *(float4*)&s[r * LDB + c4] = *(const float4*)&g[(r << 6) + c4];
    }
}
__device__ __forceinline__ void store_tile(const float* __restrict__ s, float* __restrict__ g) {
    for (int i = threadIdx.x; i < 1024; i += 256) {
        int r = i >> 4, c4 = (i & 15) << 2;
        *(float4*)&g[(r << 6) + c4] = *(const float4*)&s[r * LDB + c4];
    }
}

// ---------------- 4x4 register-tiled matmul: C = A @ B (256 threads) ----------------
// thread (tr,tc): rows 4tr..4tr+3, cols 4tc..4tc+3. Per k: 4 A-floats + 4 B-floats.
__device__ __forceinline__ void mm64_t4(const float* __restrict__ A, const float* __restrict__ B,
                                        float* __restrict__ C, int cstride) {
    const int r0 = (threadIdx.x >> 4) << 2;
    const int c0 = (threadIdx.x & 15) << 2;
    u64 acc[8];
#pragma unroll
    for (int i = 0; i < 8; ++i) acc[i] = 0ull;
#pragma unroll 4
    for (int k = 0; k < 64; ++k) {
        float a0 = A[r0 * LDB + k],       a1 = A[(r0 + 1) * LDB + k];
        float a2 = A[(r0 + 2) * LDB + k], a3 = A[(r0 + 3) * LDB + k];
        ulonglong2 b = *(const ulonglong2*)&B[k * LDB + c0];
        u64 p;
        p = pk2(a0, a0); acc[0] = fma2(p, b.x, acc[0]); acc[1] = fma2(p, b.y, acc[1]);
        p = pk2(a1, a1); acc[2] = fma2(p, b.x, acc[2]); acc[3] = fma2(p, b.y, acc[3]);
        p = pk2(a2, a2); acc[4] = fma2(p, b.x, acc[4]); acc[5] = fma2(p, b.y, acc[5]);
        p = pk2(a3, a3); acc[6] = fma2(p, b.x, acc[6]); acc[7] = fma2(p, b.y, acc[7]);
    }
#pragma unroll
    for (int i = 0; i < 4; ++i)
        *(ulonglong2*)&C[(r0 + i) * cstride + c0] = make_ulonglong2(acc[2 * i], acc[2 * i + 1]);
}

// out[r][c] = sum_j Bs[j][r] * B[j][c]  (both col-major rows j), 4x4 tiles.
__device__ __forceinline__ void gram_t4(const float* __restrict__ Bs, const float* __restrict__ B,
                                        float* __restrict__ out, int ostride) {
    const int r0 = (threadIdx.x >> 4) << 2;
    const int c0 = (threadIdx.x & 15) << 2;
    u64 acc[8];
#pragma unroll
    for (int i = 0; i < 8; ++i) acc[i] = 0ull;
#pragma unroll 4
    for (int j = 0; j < 64; ++j) {
        float4 u = *(const float4*)&Bs[j * LDB + r0];
        ulonglong2 b = *(const ulonglong2*)&B[j * LDB + c0];
        u64 p;
        p = pk2(u.x, u.x); acc[0] = fma2(p, b.x, acc[0]); acc[1] = fma2(p, b.y, acc[1]);
        p = pk2(u.y, u.y); acc[2] = fma2(p, b.x, acc[2]); acc[3] = fma2(p, b.y, acc[3]);
        p = pk2(u.z, u.z); acc[4] = fma2(p, b.x, acc[4]); acc[5] = fma2(p, b.y, acc[5]);
        p = pk2(u.w, u.w); acc[6] = fma2(p, b.x, acc[6]); acc[7] = fma2(p, b.y, acc[7]);
    }
#pragma unroll
    for (int i = 0; i < 4; ++i)
        *(ulonglong2*)&out[(r0 + i) * ostride + c0] = make_ulonglong2(acc[2 * i], acc[2 * i + 1]);
}

__device__ __forceinline__ float colnrm2(const float* __restrict__ B, int j, int seg, float4 v[4]) {
    const float4* c = (const float4*)(B + j * LDB + (seg << 4));
    v[0] = c[0]; v[1] = c[1]; v[2] = c[2]; v[3] = c[3];
    float n = v[0].x * v[0].x;
    n = fmaf(v[0].y, v[0].y, n); n = fmaf(v[0].z, v[0].z, n); n = fmaf(v[0].w, v[0].w, n);
    n = fmaf(v[1].x, v[1].x, n); n = fmaf(v[1].y, v[1].y, n); n = fmaf(v[1].z, v[1].z, n); n = fmaf(v[1].w, v[1].w, n);
    n = fmaf(v[2].x, v[2].x, n); n = fmaf(v[2].y, v[2].y, n); n = fmaf(v[2].z, v[2].z, n); n = fmaf(v[2].w, v[2].w, n);
    n = fmaf(v[3].x, v[3].x, n); n = fmaf(v[3].y, v[3].y, n); n = fmaf(v[3].z, v[3].z, n); n = fmaf(v[3].w, v[3].w, n);
    n += __shfl_xor_sync(0xffffffffu, n, 1);
    n += __shfl_xor_sync(0xffffffffu, n, 2);
    return n;
}

__device__ __forceinline__ void scale_store(float* __restrict__ D, int j, int seg,
                                            const float4 v[4], float f) {
    float4* d = (float4*)(D + j * LDB + (seg << 4));
    d[0] = make_float4(f * v[0].x, f * v[0].y, f * v[0].z, f * v[0].w);
    d[1] = make_float4(f * v[1].x, f * v[1].y, f * v[1].z, f * v[1].w);
    d[2] = make_float4(f * v[2].x, f * v[2].y, f * v[2].z, f * v[2].w);
    d[3] = make_float4(f * v[3].x, f * v[3].y, f * v[3].z, f * v[3].w);
}

// ---------------- one-sided Jacobi, 256 threads, tracked norms + skip ----------------
// Octet (tid>>3) owns pair k; lane sub=tid&7 handles rows [4s,4s+4)+[32+4s,..)
// -> conflict-free LDS/STS.128. Rotations with |apq| <= SKIP_TAU*sqrt(app*aqq)
// skip the store-back (octet-uniform decision).
__device__ void jacobi_onesided(float* __restrict__ B, float* __restrict__ nbuf, int sweeps) {
    const int tid = threadIdx.x;
    const int k = tid >> 3;
    const int o0 = (tid & 7) << 2;
    const int o1 = 32 + o0;
    const int jn = tid >> 2, segn = tid & 3;
    for (int sw = 0; sw < sweeps; ++sw) {
        {
            float4 v[4];
            float n = colnrm2(B, jn, segn, v);
            if (segn == 0) nbuf[jn] = n;
        }
        __syncthreads();
        int p = (k == 0) ? 0 : k;
        int q = 63 - k;
        for (int rr = 0; rr < 63; ++rr) {
            float* bp = B + p * LDB;
            float* bq = B + q * LDB;
            ulonglong2 P0 = *(ulonglong2*)(bp + o0), P1 = *(ulonglong2*)(bp + o1);
            ulonglong2 Q0 = *(ulonglong2*)(bq + o0), Q1 = *(ulonglong2*)(bq + o1);
            u64 spq = mul2(P0.x, Q0.x);
            spq = fma2(P0.y, Q0.y, spq); spq = fma2(P1.x, Q1.x, spq); spq = fma2(P1.y, Q1.y, spq);
            float a0, a1;
            up2(spq, a0, a1);
            float apq = a0 + a1;
            apq += __shfl_xor_sync(0xffffffffu, apq, 1);
            apq += __shfl_xor_sync(0xffffffffu, apq, 2);
            apq += __shfl_xor_sync(0xffffffffu, apq, 4);
            float app = nbuf[p], aqq = nbuf[q];
            if (apq * apq > SKIP_TAU * SKIP_TAU * app * aqq) {
                float zeta = (aqq - app) / (2.0f * apq);
                float t = copysignf(1.0f, zeta) / (fabsf(zeta) + sqrtf(fmaf(zeta, zeta, 1.0f)));
                float c = rsqrtf(fmaf(t, t, 1.0f));
                float s = t * c;
                u64 c2 = pk2(c, c), s2 = pk2(s, s), ns2 = pk2(-s, -s);
                ulonglong2 NP0, NP1, NQ0, NQ1;
                NP0.x = fma2(c2, P0.x, mul2(ns2, Q0.x));
                NP0.y = fma2(c2, P0.y, mul2(ns2, Q0.y));
                NP1.x = fma2(c2, P1.x, mul2(ns2, Q1.x));
                NP1.y = fma2(c2, P1.y, mul2(ns2, Q1.y));
                NQ0.x = fma2(s2, P0.x, mul2(c2, Q0.x));
                NQ0.y = fma2(s2, P0.y, mul2(c2, Q0.y));
                NQ1.x = fma2(s2, P1.x, mul2(c2, Q1.x));
                NQ1.y = fma2(s2, P1.y, mul2(c2, Q1.y));
                *(ulonglong2*)(bp + o0) = NP0; *(ulonglong2*)(bp + o1) = NP1;
                *(ulonglong2*)(bq + o0) = NQ0; *(ulonglong2*)(bq + o1) = NQ1;
                if ((tid & 7) == 0) {
                    float d = t * apq;
                    nbuf[p] = app - d;
                    nbuf[q] = aqq + d;
                }
            }
            if (k) p = (p == 63) ? 1 : p + 1;
            q = (q == 63) ? 1 : q + 1;
            __syncthreads();
        }
    }
}

// ---------------- two-sided Jacobi (only for indefinite tmean) ----------------
__device__ void jacobi_twosided(float* __restrict__ A, float* __restrict__ VT,
                                float* cbuf, float* sbuf, int sweeps) {
    const int tid = threadIdx.x;
    for (int idx = tid; idx < NN; idx += 256) {
        int r = idx >> 6, c = idx & 63;
        VT[r * LDB + c] = (r == c) ? 1.f : 0.f;
    }
    __syncthreads();
    for (int sw = 0; sw < sweeps; ++sw) {
        for (int rr = 0; rr < 63; ++rr) {
            if (tid < 32) {
                int p = (tid == 0) ? 0 : 1 + (tid - 1 + rr) % 63;
                int q = 1 + (62 - tid + rr) % 63;
                float app = A[p * LDB + p], aqq = A[q * LDB + q], apq = A[p * LDB + q];
                float c, s;
                if (fabsf(apq) > 1e-30f) {
                    float th = 0.5f * (aqq - app) / apq;
                    float t = copysignf(1.f, th) / (fabsf(th) + sqrtf(fmaf(th, th, 1.f)));
                    c = rsqrtf(fmaf(t, t, 1.f)); s = t * c;
                } else { c = 1.f; s = 0.f; }
                cbuf[tid] = c; sbuf[tid] = s;
            }
            __syncthreads();
            for (int u = tid; u < 1536; u += 256) {
                if (u < 1024) {
                    int ki = u & 31, kj = u >> 5;
                    int pi = (ki == 0) ? 0 : 1 + (ki - 1 + rr) % 63, qi = 1 + (62 - ki + rr) % 63;
                    int pj = (kj == 0) ? 0 : 1 + (kj - 1 + rr) % 63, qj = 1 + (62 - kj + rr) % 63;
                    float ci = cbuf[ki], si = sbuf[ki], cj = cbuf[kj], sj = sbuf[kj];
                    float a00 = A[pi * LDB + pj], a01 = A[pi * LDB + qj];
                    float a10 = A[qi * LDB + pj], a11 = A[qi * LDB + qj];
                    float b00 = ci * a00 - si * a10, b01 = ci * a01 - si * a11;
                    float b10 = si * a00 + ci * a10, b11 = si * a01 + ci * a11;
                    A[pi * LDB + pj] = cj * b00 - sj * b01;
                    A[pi * LDB + qj] = sj * b00 + cj * b01;
                    A[qi * LDB + pj] = cj * b10 - sj * b11;
                    A[qi * LDB + qj] = sj * b10 + cj * b11;
                } else {
                    int w = u - 1024;
                    int kk = w >> 4, c4 = (w & 15) << 2;
                    int p = (kk == 0) ? 0 : 1 + (kk - 1 + rr) % 63, q = 1 + (62 - kk + rr) % 63;
                    float c = cbuf[kk], s = sbuf[kk];
                    float4 vp = *(float4*)&VT[p * LDB + c4];
                    float4 vq = *(float4*)&VT[q * LDB + c4];
                    float4 np, nq;
                    np.x = c*vp.x - s*vq.x; np.y = c*vp.y - s*vq.y; np.z = c*vp.z - s*vq.z; np.w = c*vp.w - s*vq.w;
                    nq.x = s*vp.x + c*vq.x; nq.y = s*vp.y + c*vq.y; nq.z = s*vp.z + c*vq.z; nq.w = s*vp.w + c*vq.w;
                    *(float4*)&VT[p * LDB + c4] = np;
                    *(float4*)&VT[q * LDB + c4] = nq;
                }
            }
            __syncthreads();
        }
    }
}

// ---------------- kernel 0: arithmetic mean ----------------
__global__ __launch_bounds__(256) void mean_partial_kernel(const float* __restrict__ x) {
    const int g = blockIdx.x, tid = threadIdx.x;
    float4 acc[4] = {{0,0,0,0},{0,0,0,0},{0,0,0,0},{0,0,0,0}};
    const float4* xb = (const float4*)(x + (size_t)g * K0_NB * NN);
    for (int b = 0; b < K0_NB; ++b) {
#pragma unroll
        for (int i = 0; i < 4; ++i) {
            float4 v = xb[(size_t)b * 1024 + tid + (i << 8)];
            acc[i].x += v.x; acc[i].y += v.y; acc[i].z += v.z; acc[i].w += v.w;
        }
    }
    float4* pm = (float4*)(g_partial_mean + (size_t)g * NN);
#pragma unroll
    for (int i = 0; i < 4; ++i) pm[tid + (i << 8)] = acc[i];
}

__global__ void reduce_mean_kernel() {
    int j = blockIdx.x * 128 + threadIdx.x;
    float acc = 0.f;
    for (int g = 0; g < K0_BLOCKS; ++g) acc += g_partial_mean[(size_t)g * NN + j];
    g_mean[j] = acc * (1.0f / BATCH);
}

// ---------------- kernel 1: eigh(mean)->s,si ; eigh(G)->gsqrt ----------------
__global__ __launch_bounds__(256) void prep_kernel(const float* __restrict__ G) {
    extern __shared__ float sm[];
    float* A    = sm;
    float* Bsc  = A + 4352;
    float* nbuf = Bsc + 4352;
    const int tid = threadIdx.x;
    load_tile(blockIdx.x == 0 ? g_mean : G, A);
    __syncthreads();
    jacobi_onesided(A, nbuf, SWEEPS_SMALL);
    const int j = tid >> 2, seg = tid & 3;
    float4 v[4];
    float n = colnrm2(A, j, seg, v);
    float lam = fmaxf(sqrtf(n), EPSF);
    float inv_n = 1.0f / n;
    scale_store(Bsc, j, seg, v, sqrtf(lam) * inv_n);
    __syncthreads();
    gram_t4(Bsc, A, blockIdx.x == 0 ? g_s : g_gsqrt, 64);
    if (blockIdx.x == 0) {
        __syncthreads();
        scale_store(Bsc, j, seg, v, rsqrtf(lam) * inv_n);
        __syncthreads();
        gram_t4(Bsc, A, g_si, 64);
    }
}

// ---------------- kernel 2: per-batch logm(si x si), partial sums ----------------
__global__ __launch_bounds__(256, 4) void batch_log_kernel(const float* __restrict__ x) {
    extern __shared__ float sm[];
    float* sis  = sm;            // 4352
    float* b1   = sis + 4352;    // 4352
    float* b2   = b1 + 4352;     // 4352
    float* fbuf = b2 + 4352;     // 64
    float* nbuf = fbuf + 64;     // 64
    const int tid = threadIdx.x;
    load_tile(g_si, sis);
    __syncthreads();
    const int r0 = (tid >> 4) << 2, c0 = (tid & 15) << 2;
    const int j = tid >> 2, seg = tid & 3;
    u64 tacc[8];
#pragma unroll
    for (int i = 0; i < 8; ++i) tacc[i] = 0ull;

    for (int m = 0; m < K2_NB; ++m) {
        const float* xb = x + ((size_t)blockIdx.x * K2_NB + m) * NN;
        load_tile(xb, b1);
        __syncthreads();
        mm64_t4(sis, b1, b2, LDB);  __syncthreads();   // P = si @ x
        mm64_t4(b2, sis, b1, LDB);  __syncthreads();   // A = P @ si (symmetric)
        jacobi_onesided(b1, nbuf, SWEEPS_BATCH);       // cols b_j = lam_j u_j
        {
            float4 v[4];
            float n = colnrm2(b1, j, seg, v);
            if (seg == 0) {
                float lam = sqrtf(n);
                fbuf[j] = logf(fmaxf(lam, EPSF)) / n;   // log(lam)/lam^2
            }
        }
        __syncthreads();
        {   // tacc += sum_j f_j * b_j b_j^T  (4x4 tile at r0,c0)
#pragma unroll 4
            for (int jj = 0; jj < 64; ++jj) {
                float f = fbuf[jj];
                float4 u = *(const float4*)&b1[jj * LDB + r0];
                ulonglong2 b = *(const ulonglong2*)&b1[jj * LDB + c0];
                u64 p;
                p = pk2(f * u.x, f * u.x); tacc[0] = fma2(p, b.x, tacc[0]); tacc[1] = fma2(p, b.y, tacc[1]);
                p = pk2(f * u.y, f * u.y); tacc[2] = fma2(p, b.x, tacc[2]); tacc[3] = fma2(p, b.y, tacc[3]);
                p = pk2(f * u.z, f * u.z); tacc[4] = fma2(p, b.x, tacc[4]); tacc[5] = fma2(p, b.y, tacc[5]);
                p = pk2(f * u.w, f * u.w); tacc[6] = fma2(p, b.x, tacc[6]); tacc[7] = fma2(p, b.y, tacc[7]);
            }
        }
        __syncthreads();
    }
    float* pt = g_partial_t + (size_t)blockIdx.x * NN;
#pragma unroll
    for (int i = 0; i < 4; ++i)
        *(ulonglong2*)&pt[(r0 + i) * 64 + c0] = make_ulonglong2(tacc[2 * i], tacc[2 * i + 1]);
}

__global__ void reduce_t_kernel() {
    int j = blockIdx.x * 128 + threadIdx.x;
    float acc = 0.f;
    for (int g = 0; g < K2_BLOCKS; ++g) acc += g_partial_t[(size_t)g * NN + j];
    g_tmean[j] = acc * (1.0f / BATCH);
}

// ---------------- kernel 3: expm(tmean), center, csi, W, WT ----------------
__global__ __launch_bounds__(256) void center_kernel() {
    extern __shared__ float sm[];
    float* A  = sm;
    float* VT = A + 4352;
    float* T1 = VT + 4352;
    float* T2 = T1 + 4352;
    float* fw = T2 + 4352;
    float* cb = fw + 64;
    float* sb = cb + 32;
    float* nbuf = sb + 32;
    const int tid = threadIdx.x;

    load_tile(g_tmean, A);
    __syncthreads();
    jacobi_twosided(A, VT, cb, sb, SWEEPS_TS);
    if (tid < 64) fw[tid] = expf(A[tid * LDB + tid]);
    __syncthreads();
    for (int idx = tid; idx < NN; idx += 256) {
        int k2 = idx >> 6, i = idx & 63;
        T1[k2 * LDB + i] = fw[k2] * VT[k2 * LDB + i];
    }
    __syncthreads();
    gram_t4(T1, VT, T2, LDB);           // T2 = expm(tmean)
    __syncthreads();
    load_tile(g_s, A);
    __syncthreads();
    mm64_t4(A, T2, T1, LDB);  __syncthreads();  // T1 = s E
    mm64_t4(T1, A, T2, LDB);  __syncthreads();  // T2 = center (SPD)
    jacobi_onesided(T2, nbuf, SWEEPS_SMALL);
    {
        const int j = tid >> 2, seg = tid & 3;
        float4 v[4];
        float n = colnrm2(T2, j, seg, v);
        float lam = fmaxf(sqrtf(n), EPSF);
        float f = rsqrtf(lam) / n;
        scale_store(T1, j, seg, v, f);
    }
    __syncthreads();
    gram_t4(T1, T2, A, LDB);            // A = csi
    __syncthreads();
    load_tile(g_gsqrt, VT);
    __syncthreads();
    mm64_t4(VT, A, T1, LDB);            // T1 = g_sqrt @ csi = W
    __syncthreads();
    store_tile(T1, g_W);
    for (int idx = tid; idx < NN; idx += 256) {
        int rr = idx >> 6, cc = idx & 63;
        g_WT[(cc << 6) + rr] = T1[rr * LDB + cc];
    }
}

// ---------------- kernel 4: out_b = W x_b W^T ----------------
__global__ __launch_bounds__(256) void output_kernel(const float* __restrict__ x,
                                                     float* __restrict__ out) {
    extern __shared__ float sm[];
    float* Ws = sm;
    float* WT = Ws + 4352;
    float* xs = WT + 4352;
    float* P  = xs + 4352;
    load_tile(g_W, Ws);
    load_tile(g_WT, WT);
    load_tile(x + (size_t)blockIdx.x * NN, xs);
    __syncthreads();
    mm64_t4(Ws, xs, P, LDB);            // P = W @ x
    __syncthreads();
    mm64_t4(P, WT, out + (size_t)blockIdx.x * NN, 64);  // out = P @ W^T
}

// ---------------- launcher ----------------
extern "C" void kernel_launch(void* const* d_in, const int* in_sizes, int n_in,
                              void* d_out, int out_size) {
    const float* x;
    const float* G;
    if (in_sizes[0] == NN) { G = (const float*)d_in[0]; x = (const float*)d_in[1]; }
    else                   { x = (const float*)d_in[0]; G = (const float*)d_in[1]; }
    float* out = (float*)d_out;

    constexpr size_t SM_PREP   = (size_t)(2 * 4352 + 64) * 4;
    constexpr size_t SM_BATCH  = (size_t)(3 * 4352 + 64 + 64) * 4;
    constexpr size_t SM_CENTER = (size_t)(4 * 4352 + 64 + 32 + 32 + 64) * 4;
    constexpr size_t SM_OUT    = (size_t)(4 * 4352) * 4;

    cudaFuncSetAttribute(batch_log_kernel, cudaFuncAttributeMaxDynamicSharedMemorySize, (int)SM_BATCH);
    cudaFuncSetAttribute(center_kernel,    cudaFuncAttributeMaxDynamicSharedMemorySize, (int)SM_CENTER);
    cudaFuncSetAttribute(output_kernel,    cudaFuncAttributeMaxDynamicSharedMemorySize, (int)SM_OUT);

    mean_partial_kernel<<<K0_BLOCKS, 256>>>(x);
    reduce_mean_kernel<<<32, 128>>>();
    prep_kernel<<<2, 256, SM_PREP>>>(G);
    batch_log_kernel<<<K2_BLOCKS, 256, SM_BATCH>>>(x);
    reduce_t_kernel<<<32, 128>>>();
    center_kernel<<<1, 256, SM_CENTER>>>();
    output_kernel<<<BATCH, 256, SM_OUT>>>(x, out);
}